// round 3
// baseline (speedup 1.0000x reference)
#include <cuda_runtime.h>
#include <math.h>

// Problem constants
#define TT   1024
#define BB   64
#define DD   512
#define HH   512

// Kernel config
#define NB   128      // CTAs: 4 stages x 32 column-blocks (<= SM count, co-resident)
#define NT   256      // threads per CTA
#define KB   32       // K-block staged in smem
#define NKB  16       // 512 / 32

// -------- device scratch (no allocations allowed) --------
__device__ __align__(16) float g_xw0[2][BB * HH];
__device__ __align__(16) float g_xw1[2][BB * HH];
__device__ __align__(16) float g_h0[2][BB * HH];
__device__ __align__(16) float g_h1[2][BB * HH];
__device__ unsigned g_count;

__global__ void rnn_reset_kernel() { g_count = 0u; }

__device__ __forceinline__ void grid_sync(unsigned target) {
    __syncthreads();
    if (threadIdx.x == 0) {
        __threadfence();                 // release all prior global writes
        atomicAdd(&g_count, 1u);
        unsigned v;
        do {
            asm volatile("ld.acquire.gpu.u32 %0, [%1];" : "=r"(v) : "l"(&g_count));
        } while (v < target);
    }
    __syncthreads();
}

__global__ void __launch_bounds__(NT, 1)
rnn_persistent(const float* __restrict__ x,
               const float* __restrict__ h_t,
               const float* __restrict__ Wih0, const float* __restrict__ Whh0,
               const float* __restrict__ bih0, const float* __restrict__ bhh0,
               const float* __restrict__ Wih1, const float* __restrict__ Whh1,
               const float* __restrict__ bih1, const float* __restrict__ bhh1,
               float* __restrict__ out) {
    // Smem: A block (64 x 33 padded, conflict-free), kq-reduction buffer, bias
    __shared__ float A_s[BB][KB + 1];
    __shared__ float Red[3][64][16];
    __shared__ float bsum[16];

    const int tid    = threadIdx.x;
    const int stage  = blockIdx.x >> 5;   // 0:P0 xproj  1:S0 rec0  2:P1 proj1  3:S1 rec1
    const int cb     = blockIdx.x & 31;
    const int c_base = cb * 16;

    const int kq  = tid >> 6;     // 0..3  K-quarter
    const int pos = tid & 63;
    const int ri  = pos >> 2;     // 0..15 row-block
    const int ci  = pos & 3;      // 0..3  col-block
    const int r0  = ri * 4;
    const int c0  = ci * 4;

    const float* Wm = (stage == 0) ? Wih0 : (stage == 1) ? Whh0
                    : (stage == 2) ? Wih1 : Whh1;

    if (tid < 16) {
        float bv = 0.f;
        if (stage == 0)      bv = bih0[c_base + tid] + bhh0[c_base + tid];
        else if (stage == 2) bv = bih1[c_base + tid] + bhh1[c_base + tid];
        bsum[tid] = bv;
    }

    // Init hidden states from h_t [2,B,H]
    {
        int gid = blockIdx.x * NT + tid;
        if (gid < (BB * HH) / 4) {
            float4 v0 = __ldg((const float4*)h_t + gid);
            float4 v1 = __ldg((const float4*)(h_t + BB * HH) + gid);
            __stcg((float4*)&g_h0[0][0] + gid, v0);
            __stcg((float4*)&g_h1[0][0] + gid, v1);
        }
    }

    unsigned bar = 1;
    grid_sync(bar * NB); bar++;

    for (int it = 0; it <= TT + 2; ++it) {
        int t; bool active; const float* Ain;
        if (stage == 0)      { t = it;     active = (t < TT);            Ain = x + (size_t)(t < TT ? t : 0) * BB * DD; }
        else if (stage == 1) { t = it - 1; active = (t >= 0 && t < TT);  Ain = g_h0[t & 1]; }
        else if (stage == 2) { t = it - 2; active = (t >= 0 && t < TT);  Ain = g_h0[(t + 1) & 1]; }
        else                 { t = it - 3; active = (t >= 0 && t < TT);  Ain = g_h1[t & 1]; }

        if (active) {
            float acc[4][4];
            #pragma unroll
            for (int i = 0; i < 4; ++i)
                #pragma unroll
                for (int j = 0; j < 4; ++j) acc[i][j] = 0.f;

            for (int kb = 0; kb < NKB; ++kb) {
                // Stage A block [64 x 32] into smem (L2-coherent loads)
                #pragma unroll
                for (int j = 0; j < 2; ++j) {
                    int q  = tid + NT * j;     // 0..511 float4 ids
                    int b  = q >> 3;           // row 0..63
                    int k4 = q & 7;            // float4 within 32-wide block
                    float4 v = __ldcg((const float4*)(Ain + b * 512 + kb * KB) + k4);
                    A_s[b][k4 * 4 + 0] = v.x;
                    A_s[b][k4 * 4 + 1] = v.y;
                    A_s[b][k4 * 4 + 2] = v.z;
                    A_s[b][k4 * 4 + 3] = v.w;
                }
                __syncthreads();

                const float* wp = Wm + (size_t)(kb * KB + kq * 8) * HH + c_base + c0;
                #pragma unroll
                for (int kk = 0; kk < 8; ++kk) {
                    int kl = kq * 8 + kk;
                    float4 w = __ldg((const float4*)(wp + (size_t)kk * HH));
                    float a0 = A_s[r0 + 0][kl];
                    float a1 = A_s[r0 + 1][kl];
                    float a2 = A_s[r0 + 2][kl];
                    float a3 = A_s[r0 + 3][kl];
                    acc[0][0] += a0 * w.x; acc[0][1] += a0 * w.y; acc[0][2] += a0 * w.z; acc[0][3] += a0 * w.w;
                    acc[1][0] += a1 * w.x; acc[1][1] += a1 * w.y; acc[1][2] += a1 * w.z; acc[1][3] += a1 * w.w;
                    acc[2][0] += a2 * w.x; acc[2][1] += a2 * w.y; acc[2][2] += a2 * w.z; acc[2][3] += a2 * w.w;
                    acc[3][0] += a3 * w.x; acc[3][1] += a3 * w.y; acc[3][2] += a3 * w.z; acc[3][3] += a3 * w.w;
                }
                __syncthreads();
            }

            // Reduce across the 4 K-quarters
            if (kq != 0) {
                #pragma unroll
                for (int i = 0; i < 4; ++i)
                    #pragma unroll
                    for (int j = 0; j < 4; ++j)
                        Red[kq - 1][pos][i * 4 + j] = acc[i][j];
            }
            __syncthreads();

            if (kq == 0) {
                #pragma unroll
                for (int i = 0; i < 4; ++i)
                    #pragma unroll
                    for (int j = 0; j < 4; ++j)
                        acc[i][j] += Red[0][pos][i * 4 + j]
                                   + Red[1][pos][i * 4 + j]
                                   + Red[2][pos][i * 4 + j];

                float* dst;
                const float* xwsrc = nullptr;
                float* dst2 = nullptr;
                if (stage == 0)      { dst = g_xw0[it & 1]; }
                else if (stage == 1) { xwsrc = g_xw0[t & 1]; dst = g_h0[(t + 1) & 1]; }
                else if (stage == 2) { dst = g_xw1[t & 1]; }
                else                 { xwsrc = g_xw1[t & 1]; dst = g_h1[(t + 1) & 1];
                                       dst2 = out + (size_t)t * BB * HH; }
                const bool dotanh = (stage & 1);

                #pragma unroll
                for (int ir = 0; ir < 4; ++ir) {
                    int off = (r0 + ir) * HH + c_base + c0;
                    float v0 = acc[ir][0], v1 = acc[ir][1], v2 = acc[ir][2], v3 = acc[ir][3];
                    if (dotanh) {
                        float4 xw = __ldcg((const float4*)(xwsrc + off));
                        v0 = tanhf(v0 + xw.x);
                        v1 = tanhf(v1 + xw.y);
                        v2 = tanhf(v2 + xw.z);
                        v3 = tanhf(v3 + xw.w);
                    } else {
                        v0 += bsum[c0 + 0];
                        v1 += bsum[c0 + 1];
                        v2 += bsum[c0 + 2];
                        v3 += bsum[c0 + 3];
                    }
                    float4 o = make_float4(v0, v1, v2, v3);
                    __stcg((float4*)(dst + off), o);
                    if (dst2) *(float4*)(dst2 + off) = o;
                }
            }
        }

        grid_sync(bar * NB); bar++;
    }

    // Final hidden states -> out[T*B*H ..]; both layers end in slot (T & 1) == 0
    {
        int gid = blockIdx.x * NT + tid;
        if (gid < (BB * HH) / 4) {
            float4 a = __ldcg((const float4*)&g_h0[0][0] + gid);
            float4 b = __ldcg((const float4*)&g_h1[0][0] + gid);
            *((float4*)(out + (size_t)TT * BB * HH) + gid) = a;
            *((float4*)(out + (size_t)TT * BB * HH + BB * HH) + gid) = b;
        }
    }
}

extern "C" void kernel_launch(void* const* d_in, const int* in_sizes, int n_in,
                              void* d_out, int out_size) {
    (void)in_sizes; (void)n_in; (void)out_size;
    const float* x    = (const float*)d_in[0];
    const float* h_t  = (const float*)d_in[1];
    const float* Wih0 = (const float*)d_in[2];
    const float* Whh0 = (const float*)d_in[3];
    const float* bih0 = (const float*)d_in[4];
    const float* bhh0 = (const float*)d_in[5];
    const float* Wih1 = (const float*)d_in[6];
    const float* Whh1 = (const float*)d_in[7];
    const float* bih1 = (const float*)d_in[8];
    const float* bhh1 = (const float*)d_in[9];
    float* out = (float*)d_out;

    rnn_reset_kernel<<<1, 1>>>();
    rnn_persistent<<<NB, NT>>>(x, h_t, Wih0, Whh0, bih0, bhh0,
                               Wih1, Whh1, bih1, bhh1, out);
}

// round 6
// speedup vs baseline: 1.5220x; 1.5220x over previous
#include <cuda_runtime.h>
#include <math.h>

// Problem constants
#define TT   1024
#define BB   64
#define DD   512
#define HH   512

// Kernel config
#define NB   128      // CTAs: 4 stages x 32 column-blocks (co-resident on <=148 SMs)
#define NT   256      // threads per CTA
#define KB   64       // K-block staged in smem (double-buffered)
#define NKB  8        // 512 / 64

// -------- device scratch (no allocations allowed) --------
__device__ __align__(16) float g_xw0[2][BB * HH];
__device__ __align__(16) float g_xw1[2][BB * HH];
__device__ __align__(16) float g_h0[2][BB * HH];
__device__ __align__(16) float g_h1[2][BB * HH];
__device__ unsigned g_count;

__global__ void rnn_reset_kernel() { g_count = 0u; }

__device__ __forceinline__ void grid_sync(unsigned target) {
    __syncthreads();
    if (threadIdx.x == 0) {
        __threadfence();                 // release all prior global writes
        atomicAdd(&g_count, 1u);
        unsigned v;
        do {
            asm volatile("ld.acquire.gpu.u32 %0, [%1];" : "=r"(v) : "l"(&g_count));
        } while (v < target);
    }
    __syncthreads();
}

__global__ void __launch_bounds__(NT, 1)
rnn_persistent(const float* __restrict__ x,
               const float* __restrict__ h_t,
               const float* __restrict__ Wih0, const float* __restrict__ Whh0,
               const float* __restrict__ bih0, const float* __restrict__ bhh0,
               const float* __restrict__ Wih1, const float* __restrict__ Whh1,
               const float* __restrict__ bih1, const float* __restrict__ bhh1,
               float* __restrict__ out) {
    // Double-buffered A block (64 x 64, pad to 65 for conflict-free column reads),
    // kq-reduction buffer, fused bias. Static smem total: 33,280 + 12,288 + 64 < 48K.
    __shared__ float A_s[2][BB][KB + 1];
    __shared__ float Red[3][64][16];
    __shared__ float bsum[16];

    const int tid    = threadIdx.x;
    const int stage  = blockIdx.x >> 5;   // 0:P0 xproj  1:S0 rec0  2:P1 proj1  3:S1 rec1
    const int cb     = blockIdx.x & 31;
    const int c_base = cb * 16;

    const int kq  = tid >> 6;     // 0..3  K-quarter
    const int pos = tid & 63;
    const int ri  = pos >> 2;     // 0..15 row-block
    const int ci  = pos & 3;      // 0..3  col-block
    const int r0  = ri * 4;
    const int c0  = ci * 4;

    const float* Wm = (stage == 0) ? Wih0 : (stage == 1) ? Whh0
                    : (stage == 2) ? Wih1 : Whh1;

    if (tid < 16) {
        float bv = 0.f;
        if (stage == 0)      bv = bih0[c_base + tid] + bhh0[c_base + tid];
        else if (stage == 2) bv = bih1[c_base + tid] + bhh1[c_base + tid];
        bsum[tid] = bv;
    }

    // Init hidden states from h_t [2,B,H]
    {
        int gid = blockIdx.x * NT + tid;
        if (gid < (BB * HH) / 4) {
            float4 v0 = __ldg((const float4*)h_t + gid);
            float4 v1 = __ldg((const float4*)(h_t + BB * HH) + gid);
            __stcg((float4*)&g_h0[0][0] + gid, v0);
            __stcg((float4*)&g_h1[0][0] + gid, v1);
        }
    }

    unsigned bar = 1;
    grid_sync(bar * NB); bar++;

    // Per-thread staging coordinates (4 float4 per thread per 64-wide k-block)
    int sb[4], sk4[4];
    #pragma unroll
    for (int j = 0; j < 4; ++j) {
        int q = tid + NT * j;       // 0..1023 float4 ids
        sb[j]  = q >> 4;            // row 0..63
        sk4[j] = q & 15;            // float4 within 64-wide block
    }

    for (int it = 0; it <= TT + 2; ++it) {
        int t; bool active; const float* Ain;
        if (stage == 0)      { t = it;     active = (t < TT);            Ain = x + (size_t)(t < TT ? t : 0) * BB * DD; }
        else if (stage == 1) { t = it - 1; active = (t >= 0 && t < TT);  Ain = g_h0[t & 1]; }
        else if (stage == 2) { t = it - 2; active = (t >= 0 && t < TT);  Ain = g_h0[(t + 1) & 1]; }
        else                 { t = it - 3; active = (t >= 0 && t < TT);  Ain = g_h1[t & 1]; }

        if (active) {
            float acc[4][4];
            #pragma unroll
            for (int i = 0; i < 4; ++i)
                #pragma unroll
                for (int j = 0; j < 4; ++j) acc[i][j] = 0.f;

            float4 pre[4];
            // Prologue: fetch k-block 0 into buffer 0
            #pragma unroll
            for (int j = 0; j < 4; ++j)
                pre[j] = __ldcg((const float4*)(Ain + sb[j] * 512) + sk4[j]);
            #pragma unroll
            for (int j = 0; j < 4; ++j) {
                float* d = &A_s[0][sb[j]][sk4[j] * 4];
                d[0] = pre[j].x; d[1] = pre[j].y; d[2] = pre[j].z; d[3] = pre[j].w;
            }
            __syncthreads();

            for (int kb = 0; kb < NKB; ++kb) {
                const int cur = kb & 1;
                // Prefetch next block into registers while computing this one
                if (kb + 1 < NKB) {
                    #pragma unroll
                    for (int j = 0; j < 4; ++j)
                        pre[j] = __ldcg((const float4*)(Ain + sb[j] * 512 + (kb + 1) * KB) + sk4[j]);
                }

                const float* wp = Wm + (size_t)(kb * KB + kq * 16) * HH + c_base + c0;
                #pragma unroll
                for (int kk = 0; kk < 16; ++kk) {
                    const int kl = kq * 16 + kk;
                    float4 w = __ldg((const float4*)(wp + (size_t)kk * HH));
                    float a0 = A_s[cur][r0 + 0][kl];
                    float a1 = A_s[cur][r0 + 1][kl];
                    float a2 = A_s[cur][r0 + 2][kl];
                    float a3 = A_s[cur][r0 + 3][kl];
                    acc[0][0] += a0 * w.x; acc[0][1] += a0 * w.y; acc[0][2] += a0 * w.z; acc[0][3] += a0 * w.w;
                    acc[1][0] += a1 * w.x; acc[1][1] += a1 * w.y; acc[1][2] += a1 * w.z; acc[1][3] += a1 * w.w;
                    acc[2][0] += a2 * w.x; acc[2][1] += a2 * w.y; acc[2][2] += a2 * w.z; acc[2][3] += a2 * w.w;
                    acc[3][0] += a3 * w.x; acc[3][1] += a3 * w.y; acc[3][2] += a3 * w.z; acc[3][3] += a3 * w.w;
                }

                // Store prefetched block into the other buffer, then one sync
                if (kb + 1 < NKB) {
                    #pragma unroll
                    for (int j = 0; j < 4; ++j) {
                        float* d = &A_s[cur ^ 1][sb[j]][sk4[j] * 4];
                        d[0] = pre[j].x; d[1] = pre[j].y; d[2] = pre[j].z; d[3] = pre[j].w;
                    }
                }
                __syncthreads();
            }

            // Reduce across the 4 K-quarters
            if (kq != 0) {
                #pragma unroll
                for (int i = 0; i < 4; ++i)
                    #pragma unroll
                    for (int j = 0; j < 4; ++j)
                        Red[kq - 1][pos][i * 4 + j] = acc[i][j];
            }
            __syncthreads();

            if (kq == 0) {
                #pragma unroll
                for (int i = 0; i < 4; ++i)
                    #pragma unroll
                    for (int j = 0; j < 4; ++j)
                        acc[i][j] += Red[0][pos][i * 4 + j]
                                   + Red[1][pos][i * 4 + j]
                                   + Red[2][pos][i * 4 + j];

                float* dst;
                const float* xwsrc = nullptr;
                float* dst2 = nullptr;
                if (stage == 0)      { dst = g_xw0[it & 1]; }
                else if (stage == 1) { xwsrc = g_xw0[t & 1]; dst = g_h0[(t + 1) & 1]; }
                else if (stage == 2) { dst = g_xw1[t & 1]; }
                else                 { xwsrc = g_xw1[t & 1]; dst = g_h1[(t + 1) & 1];
                                       dst2 = out + (size_t)t * BB * HH; }
                const bool dotanh = (stage & 1);

                #pragma unroll
                for (int ir = 0; ir < 4; ++ir) {
                    int off = (r0 + ir) * HH + c_base + c0;
                    float v0 = acc[ir][0], v1 = acc[ir][1], v2 = acc[ir][2], v3 = acc[ir][3];
                    if (dotanh) {
                        float4 xw = __ldcg((const float4*)(xwsrc + off));
                        v0 = tanhf(v0 + xw.x);
                        v1 = tanhf(v1 + xw.y);
                        v2 = tanhf(v2 + xw.z);
                        v3 = tanhf(v3 + xw.w);
                    } else {
                        v0 += bsum[c0 + 0];
                        v1 += bsum[c0 + 1];
                        v2 += bsum[c0 + 2];
                        v3 += bsum[c0 + 3];
                    }
                    float4 o = make_float4(v0, v1, v2, v3);
                    __stcg((float4*)(dst + off), o);
                    if (dst2) *(float4*)(dst2 + off) = o;
                }
            }
        }

        grid_sync(bar * NB); bar++;
    }

    // Final hidden states -> out[T*B*H ..]; both layers end in slot (T & 1) == 0
    {
        int gid = blockIdx.x * NT + tid;
        if (gid < (BB * HH) / 4) {
            float4 a = __ldcg((const float4*)&g_h0[0][0] + gid);
            float4 b = __ldcg((const float4*)&g_h1[0][0] + gid);
            *((float4*)(out + (size_t)TT * BB * HH) + gid) = a;
            *((float4*)(out + (size_t)TT * BB * HH + BB * HH) + gid) = b;
        }
    }
}

extern "C" void kernel_launch(void* const* d_in, const int* in_sizes, int n_in,
                              void* d_out, int out_size) {
    (void)in_sizes; (void)n_in; (void)out_size;
    const float* x    = (const float*)d_in[0];
    const float* h_t  = (const float*)d_in[1];
    const float* Wih0 = (const float*)d_in[2];
    const float* Whh0 = (const float*)d_in[3];
    const float* bih0 = (const float*)d_in[4];
    const float* bhh0 = (const float*)d_in[5];
    const float* Wih1 = (const float*)d_in[6];
    const float* Whh1 = (const float*)d_in[7];
    const float* bih1 = (const float*)d_in[8];
    const float* bhh1 = (const float*)d_in[9];
    float* out = (float*)d_out;

    rnn_reset_kernel<<<1, 1>>>();
    rnn_persistent<<<NB, NT>>>(x, h_t, Wih0, Whh0, bih0, bhh0,
                               Wih1, Whh1, bih1, bhh1, out);
}